// round 1
// baseline (speedup 1.0000x reference)
#include <cuda_runtime.h>
#include <math.h>
#include <stdint.h>

#define NB 4
#define NC 64
#define NN 8192
#define NO 128
#define KK 20

// ---------------- scratch (device globals: allocation-free) ----------------
__device__ float g_xt[NB * NN * NC];   // x transposed: [b][n][c]  (8 MB)
__device__ float g_xx[NB * NN];        // squared norms
__device__ int   g_idx[NB * NN * KK];  // top-K neighbor indices

// ============================================================================
// K1: transpose x[b][c][n] -> xt[b][n][c], and xx[b][n] = sum_c x^2
// grid (NN/64, NB), block 256
// ============================================================================
__global__ __launch_bounds__(256) void k_prep(const float* __restrict__ x) {
    __shared__ float t[64 * 65];
    int b = blockIdx.y;
    int n0 = blockIdx.x * 64;
    int tid = threadIdx.x;
    const float* xb = x + (size_t)b * NC * NN;

    for (int i = tid; i < 64 * 64; i += 256) {
        int c = i >> 6, nn = i & 63;           // consecutive tid -> consecutive nn (coalesced)
        t[c * 65 + nn] = xb[c * NN + n0 + nn];
    }
    __syncthreads();
    for (int i = tid; i < 64 * 64; i += 256) {
        int nn = i >> 6, c = i & 63;           // consecutive tid -> consecutive c (coalesced store)
        g_xt[((size_t)b * NN + n0 + nn) * NC + c] = t[c * 65 + nn];
    }
    if (tid < 64) {
        float s = 0.f;
        #pragma unroll
        for (int c = 0; c < 64; c++) { float v = t[c * 65 + tid]; s += v * v; }
        g_xx[b * NN + n0 + tid] = s;
    }
}

// ============================================================================
// K2: fused distance-GEMM + top-20 selection.
// CTA = 32 rows (8 warps x 4 rows), column tiles of 256.
// pd[n][m] = 2*dot - xx_n - xx_m  (same formula as reference; larger = nearer)
// Selection: per-row shared sorted list; ballot-gated serial insertion on lane 0
// (expected ~120 insertions per row across all 8192 candidates => near-free).
// dyn smem layout (floats):
//   tile  [64][260]  @0       (16640)
//   txx   [256]      @16640
//   rows  [32][65]   @16896   (2080)
//   topv  [32][20]   @18976
//   topi  [32][20]   @19616   (total 20256 floats = 81024 B)
// ============================================================================
#define KNN_SMEM (20256 * 4)

__global__ __launch_bounds__(256) void k_knn(const float* __restrict__ x) {
    extern __shared__ float sm[];
    float* s_tile = sm;                  // [64][260]
    float* s_txx  = sm + 16640;          // [256]
    float* s_rows = sm + 16896;          // [32][65]
    float* s_topv = sm + 18976;          // [32][20]
    int*   s_topi = (int*)(sm + 19616);  // [32][20]

    int b   = blockIdx.y;
    int r0  = blockIdx.x * 32;
    int tid = threadIdx.x, lane = tid & 31, wid = tid >> 5;
    const float* xb = x + (size_t)b * NC * NN;

    // load the 32 row vectors (padded rows: conflict-free broadcast reads later)
    for (int i = tid; i < 32 * 64; i += 256) {
        int rr = i & 31, c = i >> 5;     // consecutive tid -> consecutive rr (coalesced gmem)
        s_rows[rr * 65 + c] = xb[c * NN + r0 + rr];
    }
    for (int i = tid; i < 32 * KK; i += 256) { s_topv[i] = -INFINITY; s_topi[i] = 0; }

    int row0 = wid * 4;
    float rxx[4];
    #pragma unroll
    for (int j = 0; j < 4; j++) rxx[j] = g_xx[b * NN + r0 + row0 + j];

    for (int m0 = 0; m0 < NN; m0 += 256) {
        __syncthreads();
        for (int i = tid; i < 64 * 256; i += 256) {
            int c = i >> 8, mm = i & 255;                 // coalesced load, conflict-free STS
            s_tile[c * 260 + mm] = xb[c * NN + m0 + mm];
        }
        s_txx[tid] = g_xx[b * NN + m0 + tid];
        __syncthreads();

        // each lane: 4 rows x 8 cols (cols 4*lane..+3 and 128+4*lane..+3)
        float acc[32];
        #pragma unroll
        for (int q = 0; q < 32; q++) acc[q] = 0.f;

        #pragma unroll 4
        for (int c = 0; c < 64; c++) {
            const float4 a = *(const float4*)&s_tile[c * 260 + 4 * lane];
            const float4 e = *(const float4*)&s_tile[c * 260 + 128 + 4 * lane];
            #pragma unroll
            for (int j = 0; j < 4; j++) {
                float rv = s_rows[(row0 + j) * 65 + c];
                acc[j*8+0] += rv * a.x; acc[j*8+1] += rv * a.y;
                acc[j*8+2] += rv * a.z; acc[j*8+3] += rv * a.w;
                acc[j*8+4] += rv * e.x; acc[j*8+5] += rv * e.y;
                acc[j*8+6] += rv * e.z; acc[j*8+7] += rv * e.w;
            }
        }

        // selection per row
        #pragma unroll
        for (int j = 0; j < 4; j++) {
            int row = row0 + j;
            float* topv = s_topv + row * KK;
            int*   topi = s_topi + row * KK;
            float pd[8];
            #pragma unroll
            for (int q = 0; q < 8; q++) {
                int mm = (q < 4) ? (4 * lane + q) : (124 + 4 * lane + q);
                pd[q] = 2.f * acc[j * 8 + q] - rxx[j] - s_txx[mm];
            }
            float lmax = pd[0];
            #pragma unroll
            for (int q = 1; q < 8; q++) lmax = fmaxf(lmax, pd[q]);

            float thr = topv[KK - 1];
            unsigned act = __ballot_sync(0xffffffffu, lmax > thr);
            while (act) {
                int src = __ffs(act) - 1; act &= act - 1;
                #pragma unroll
                for (int q = 0; q < 8; q++) {
                    float v = __shfl_sync(0xffffffffu, pd[q], src);
                    if (lane == 0 && v > topv[KK - 1]) {
                        int mmq = (q < 4) ? (4 * src + q) : (124 + 4 * src + q);
                        int p = KK - 1;
                        while (p > 0 && topv[p - 1] < v) {
                            topv[p] = topv[p - 1]; topi[p] = topi[p - 1]; p--;
                        }
                        topv[p] = v; topi[p] = m0 + mmq;
                    }
                }
                __syncwarp();
            }
        }
    }
    __syncwarp();
    #pragma unroll
    for (int j = 0; j < 4; j++) {
        int row = row0 + j;
        if (lane < KK)
            g_idx[((size_t)b * NN + r0 + row) * KK + lane] = s_topi[row * KK + lane];
    }
}

// ============================================================================
// K3: per-point gated MLP. Warp per point, persistent grid (148 CTAs x 8 warps).
// Algebra: softmax over k sums to 1 => center-half of g equals x_n exactly;
// only h[:, d<64] is needed for the gates that matter.
//   h[k][d] = sum_{c<64} diff[k][c] * W1[d][c]  +  sum_{c<64} xn[c] * W1[d][64+c]
//   gate = softmax_k(h);  gA[c] = (sum_k diff[k][c] e[k][c]) / s[c]  (c<64)
//   g[64+c] = xn[c];  out[o] = sum_{c<128} W2[o][c] g[c]
// dyn smem (floats):
//   sW1h [128][68]  @0      (8704)   sW1h[cin][d], d<64
//   sW2  [128][132] @8704   (16896)  sW2[c][o]
//   sdiff[8][20][64]@25600  (10240)
//   sxn  [8][64]    @35840
//   sg   [8][128]   @36352  (total 37376 floats = 149504 B)
// ============================================================================
#define MLP_SMEM (37376 * 4)

__global__ __launch_bounds__(256) void k_mlp(const float* __restrict__ W1,
                                             const float* __restrict__ W2,
                                             float* __restrict__ out) {
    extern __shared__ float sm[];
    float* sW1h  = sm;               // [cin*68 + d]
    float* sW2   = sm + 8704;        // [c*132 + o]
    float* sdiff = sm + 25600;       // [(wid*20+k)*64 + c]
    float* sxn   = sm + 35840;       // [wid*64 + c]
    float* sg    = sm + 36352;       // [wid*128 + c]

    int tid = threadIdx.x, lane = tid & 31, wid = tid >> 5;

    for (int i = tid; i < 64 * 128; i += 256) {     // W1 rows d<64, transposed
        int d = i >> 7, c = i & 127;
        sW1h[c * 68 + d] = W1[i];
    }
    for (int i = tid; i < 128 * 128; i += 256) {    // W2 transposed
        int o = i >> 7, c = i & 127;
        sW2[c * 132 + o] = W2[i];
    }
    __syncthreads();

    int gw = blockIdx.x * 8 + wid;   // global warp id: 0..1183
    for (int p = gw; p < NB * NN; p += 148 * 8) {
        int b = p >> 13, n = p & (NN - 1);
        const float* xc = g_xt + (size_t)p * 64;
        float xn0 = xc[lane], xn1 = xc[lane + 32];
        sxn[wid * 64 + lane] = xn0;
        sxn[wid * 64 + lane + 32] = xn1;

        int midx = 0;
        if (lane < KK) midx = g_idx[p * KK + lane];
        #pragma unroll
        for (int k = 0; k < KK; k++) {
            int m = __shfl_sync(0xffffffffu, midx, k);
            const float* xm = g_xt + ((size_t)b * NN + m) * 64;
            sdiff[(wid * 20 + k) * 64 + lane]      = xm[lane]      - xn0;
            sdiff[(wid * 20 + k) * 64 + lane + 32] = xm[lane + 32] - xn1;
        }
        __syncwarp();

        // h for d = 2*lane, 2*lane+1  (all d<64 covered by the warp)
        const float* dif = sdiff + wid * 20 * 64;
        float h0[KK], h1[KK];
        #pragma unroll
        for (int k = 0; k < KK; k++) { h0[k] = 0.f; h1[k] = 0.f; }
        float hc0 = 0.f, hc1 = 0.f;
        #pragma unroll 2
        for (int c = 0; c < 64; c++) {
            const float2 w  = *(const float2*)&sW1h[c * 68 + 2 * lane];
            const float2 w2 = *(const float2*)&sW1h[(64 + c) * 68 + 2 * lane];
            float xnc = sxn[wid * 64 + c];
            hc0 += xnc * w2.x; hc1 += xnc * w2.y;
            #pragma unroll
            for (int k = 0; k < KK; k++) {
                float dv = dif[k * 64 + c];
                h0[k] += dv * w.x; h1[k] += dv * w.y;
            }
        }
        // softmax over k (two d-columns per lane)
        float m0v = -INFINITY, m1v = -INFINITY;
        #pragma unroll
        for (int k = 0; k < KK; k++) {
            h0[k] += hc0; h1[k] += hc1;
            m0v = fmaxf(m0v, h0[k]); m1v = fmaxf(m1v, h1[k]);
        }
        float s0 = 0.f, s1 = 0.f;
        #pragma unroll
        for (int k = 0; k < KK; k++) {
            h0[k] = __expf(h0[k] - m0v); s0 += h0[k];
            h1[k] = __expf(h1[k] - m1v); s1 += h1[k];
        }
        float i0 = 1.f / s0, i1 = 1.f / s1;

        // gA for c = 2*lane, 2*lane+1
        float ga = 0.f, gb = 0.f;
        #pragma unroll
        for (int k = 0; k < KK; k++) {
            const float2 dv = *(const float2*)&dif[k * 64 + 2 * lane];
            ga += dv.x * h0[k]; gb += dv.y * h1[k];
        }
        float* gp = sg + wid * 128;
        gp[2 * lane]     = ga * i0;
        gp[2 * lane + 1] = gb * i1;
        gp[64 + lane]    = xn0;      // center half: softmax sums to 1
        gp[96 + lane]    = xn1;
        __syncwarp();

        // out[o] = sum_c W2[o][c] * g[c] ; lane owns o = 4*lane..+3
        float o0 = 0.f, o1 = 0.f, o2 = 0.f, o3 = 0.f;
        #pragma unroll 4
        for (int c = 0; c < 128; c++) {
            float gv = gp[c];
            const float4 w = *(const float4*)&sW2[c * 132 + 4 * lane];
            o0 += gv * w.x; o1 += gv * w.y; o2 += gv * w.z; o3 += gv * w.w;
        }
        float* op = out + (size_t)b * NO * NN + n;
        op[(4 * lane + 0) * NN] = o0;
        op[(4 * lane + 1) * NN] = o1;
        op[(4 * lane + 2) * NN] = o2;
        op[(4 * lane + 3) * NN] = o3;
        __syncwarp();
    }
}

// ============================================================================
extern "C" void kernel_launch(void* const* d_in, const int* in_sizes, int n_in,
                              void* d_out, int out_size) {
    const float* x  = (const float*)d_in[0];
    const float* W1 = (const float*)d_in[1];
    const float* W2 = (const float*)d_in[2];
    float* out = (float*)d_out;

    // Non-stream API: executes immediately, not captured; idempotent per call.
    cudaFuncSetAttribute(k_knn, cudaFuncAttributeMaxDynamicSharedMemorySize, KNN_SMEM);
    cudaFuncSetAttribute(k_mlp, cudaFuncAttributeMaxDynamicSharedMemorySize, MLP_SMEM);

    dim3 g1(NN / 64, NB);
    k_prep<<<g1, 256>>>(x);
    dim3 g2(NN / 32, NB);
    k_knn<<<g2, 256, KNN_SMEM>>>(x);
    k_mlp<<<148, 256, MLP_SMEM>>>(W1, W2, out);
}

// round 2
// speedup vs baseline: 2.1429x; 2.1429x over previous
#include <cuda_runtime.h>
#include <math.h>
#include <stdint.h>

#define NB 4
#define NC 64
#define NN 8192
#define NO 128
#define KK 20

// ---------------- scratch (device globals: allocation-free) ----------------
__device__ float g_xt[NB * NN * NC];   // x transposed: [b][n][c]  (8 MB)
__device__ float g_xx[NB * NN];        // squared norms
__device__ int   g_idx[NB * NN * KK];  // top-K neighbor indices (UNSORTED set)

// ============================================================================
// K1: transpose x[b][c][n] -> xt[b][n][c], and xx[b][n] = sum_c x^2
// ============================================================================
__global__ __launch_bounds__(256) void k_prep(const float* __restrict__ x) {
    __shared__ float t[64 * 65];
    int b = blockIdx.y;
    int n0 = blockIdx.x * 64;
    int tid = threadIdx.x;
    const float* xb = x + (size_t)b * NC * NN;

    for (int i = tid; i < 64 * 64; i += 256) {
        int c = i >> 6, nn = i & 63;
        t[c * 65 + nn] = xb[c * NN + n0 + nn];
    }
    __syncthreads();
    for (int i = tid; i < 64 * 64; i += 256) {
        int nn = i >> 6, c = i & 63;
        g_xt[((size_t)b * NN + n0 + nn) * NC + c] = t[c * 65 + nn];
    }
    if (tid < 64) {
        float s = 0.f;
        #pragma unroll
        for (int c = 0; c < 64; c++) { float v = t[c * 65 + tid]; s += v * v; }
        g_xx[b * NN + n0 + tid] = s;
    }
}

// ============================================================================
// K2: fused distance-GEMM + warp-distributed top-20.
// CTA = 32 rows (8 warps x 4 rows), column tiles of 256.
// Ranking key: pd = dot(n,m) - 0.5*||m||^2   (row term dropped, x2 folded:
// strictly monotone in the reference's 2*dot - xx_n - xx_m => same set).
// Top-20 per row lives distributed: lane t (t<20) holds entry t (val+idx regs).
// Insert: uniform branch -> ballot(val==curmin) -> one lane swaps -> bfly min.
// Output: unsorted set (K3 is order-invariant: softmax over k).
// dyn smem (floats): tile[64][260] @0 (16640) | txxh[256] @16640 | rows[32][65] @16896
// ============================================================================
#define KNN_SMEM (18976 * 4)

__global__ __launch_bounds__(256) void k_knn(const float* __restrict__ x) {
    extern __shared__ float sm[];
    float* s_tile = sm;                  // [64][260]
    float* s_txxh = sm + 16640;          // [256]  0.5*||m||^2
    float* s_rows = sm + 16896;          // [32][65]

    int b   = blockIdx.y;
    int r0  = blockIdx.x * 32;
    int tid = threadIdx.x, lane = tid & 31, wid = tid >> 5;
    const float* xb = x + (size_t)b * NC * NN;

    for (int i = tid; i < 32 * 64; i += 256) {
        int rr = i & 31, c = i >> 5;
        s_rows[rr * 65 + c] = xb[c * NN + r0 + rr];
    }

    int row0 = wid * 4;
    // distributed top-20 state: lane t<20 holds entry t of each of the 4 rows
    float val[4]; int idxr[4]; float rmin[4];
    #pragma unroll
    for (int j = 0; j < 4; j++) {
        val[j] = (lane < KK) ? -INFINITY : INFINITY;
        idxr[j] = 0;
        rmin[j] = -INFINITY;
    }

    for (int m0 = 0; m0 < NN; m0 += 256) {
        __syncthreads();
        // vectorized tile load: 64 rows x 256 cols
        for (int i = tid; i < 64 * 64; i += 256) {
            int c = i >> 6, m4 = i & 63;
            float4 v = *(const float4*)&xb[c * NN + m0 + 4 * m4];
            *(float4*)&s_tile[c * 260 + 4 * m4] = v;
        }
        s_txxh[tid] = 0.5f * g_xx[b * NN + m0 + tid];
        __syncthreads();

        // each lane: 4 rows x 8 cols
        float acc[32];
        #pragma unroll
        for (int q = 0; q < 32; q++) acc[q] = 0.f;

        #pragma unroll 4
        for (int c = 0; c < 64; c++) {
            const float4 a = *(const float4*)&s_tile[c * 260 + 4 * lane];
            const float4 e = *(const float4*)&s_tile[c * 260 + 128 + 4 * lane];
            #pragma unroll
            for (int j = 0; j < 4; j++) {
                float rv = s_rows[(row0 + j) * 65 + c];
                acc[j*8+0] += rv * a.x; acc[j*8+1] += rv * a.y;
                acc[j*8+2] += rv * a.z; acc[j*8+3] += rv * a.w;
                acc[j*8+4] += rv * e.x; acc[j*8+5] += rv * e.y;
                acc[j*8+6] += rv * e.z; acc[j*8+7] += rv * e.w;
            }
        }

        // selection per row: warp-uniform, no divergence, no smem
        #pragma unroll
        for (int j = 0; j < 4; j++) {
            float pd[8];
            #pragma unroll
            for (int q = 0; q < 8; q++) {
                int mm = (q < 4) ? (4 * lane + q) : (124 + 4 * lane + q);
                pd[q] = acc[j * 8 + q] - s_txxh[mm];
            }
            float lmax = pd[0];
            #pragma unroll
            for (int q = 1; q < 8; q++) lmax = fmaxf(lmax, pd[q]);

            unsigned act = __ballot_sync(0xffffffffu, lmax > rmin[j]);
            while (act) {
                int src = __ffs(act) - 1; act &= act - 1;
                #pragma unroll
                for (int q = 0; q < 8; q++) {
                    float v = __shfl_sync(0xffffffffu, pd[q], src);
                    if (v > rmin[j]) {            // uniform branch (v, rmin uniform)
                        int mmq = (q < 4) ? (4 * src + q) : (124 + 4 * src + q);
                        unsigned eq = __ballot_sync(0xffffffffu, val[j] == rmin[j]);
                        int sel = __ffs(eq) - 1;
                        if (lane == sel) { val[j] = v; idxr[j] = m0 + mmq; }
                        float mv = val[j];
                        #pragma unroll
                        for (int off = 16; off > 0; off >>= 1)
                            mv = fminf(mv, __shfl_xor_sync(0xffffffffu, mv, off));
                        rmin[j] = mv;
                    }
                }
            }
        }
    }

    if (lane < KK) {
        #pragma unroll
        for (int j = 0; j < 4; j++)
            g_idx[((size_t)b * NN + r0 + row0 + j) * KK + lane] = idxr[j];
    }
}

// ============================================================================
// K3: per-point gated MLP. Warp per point, persistent grid.
// softmax over k sums to 1 => center-half of gated feats equals x_n exactly;
// only h[:, d<64] needed. float2-ized h-loop (LDS.64 broadcasts).
// dyn smem (floats):
//   sW1h [128][68]  @0      sW1h[cin][d], d<64
//   sW2  [128][132] @8704   sW2[c][o]
//   sdiff[8][20][64]@25600
//   sxn  [8][64]    @35840
//   sg   [8][128]   @36352  (total 37376 floats)
// ============================================================================
#define MLP_SMEM (37376 * 4)

__global__ __launch_bounds__(256) void k_mlp(const float* __restrict__ W1,
                                             const float* __restrict__ W2,
                                             float* __restrict__ out) {
    extern __shared__ float sm[];
    float* sW1h  = sm;               // [cin*68 + d]
    float* sW2   = sm + 8704;        // [c*132 + o]
    float* sdiff = sm + 25600;       // [(wid*20+k)*64 + c]
    float* sxn   = sm + 35840;       // [wid*64 + c]
    float* sg    = sm + 36352;       // [wid*128 + c]

    int tid = threadIdx.x, lane = tid & 31, wid = tid >> 5;

    for (int i = tid; i < 64 * 128; i += 256) {
        int d = i >> 7, c = i & 127;
        sW1h[c * 68 + d] = W1[i];
    }
    for (int i = tid; i < 128 * 128; i += 256) {
        int o = i >> 7, c = i & 127;
        sW2[c * 132 + o] = W2[i];
    }
    __syncthreads();

    int gw = blockIdx.x * 8 + wid;
    for (int p = gw; p < NB * NN; p += 148 * 8) {
        int b = p >> 13, n = p & (NN - 1);
        const float* xc = g_xt + (size_t)p * 64;
        float xn0 = xc[lane], xn1 = xc[lane + 32];
        sxn[wid * 64 + lane] = xn0;
        sxn[wid * 64 + lane + 32] = xn1;

        int midx = 0;
        if (lane < KK) midx = g_idx[p * KK + lane];
        #pragma unroll
        for (int k = 0; k < KK; k++) {
            int m = __shfl_sync(0xffffffffu, midx, k);
            const float* xm = g_xt + ((size_t)b * NN + m) * 64;
            sdiff[(wid * 20 + k) * 64 + lane]      = xm[lane]      - xn0;
            sdiff[(wid * 20 + k) * 64 + lane + 32] = xm[lane + 32] - xn1;
        }
        __syncwarp();

        // h for d = 2*lane, 2*lane+1 ; float2 over c
        const float* dif = sdiff + wid * 20 * 64;
        float h0[KK], h1[KK];
        #pragma unroll
        for (int k = 0; k < KK; k++) { h0[k] = 0.f; h1[k] = 0.f; }
        float hc0 = 0.f, hc1 = 0.f;
        #pragma unroll 2
        for (int c2 = 0; c2 < 32; c2++) {
            int c = 2 * c2;
            const float2 wa0 = *(const float2*)&sW1h[c * 68 + 2 * lane];
            const float2 wa1 = *(const float2*)&sW1h[(c + 1) * 68 + 2 * lane];
            const float2 wb0 = *(const float2*)&sW1h[(64 + c) * 68 + 2 * lane];
            const float2 wb1 = *(const float2*)&sW1h[(65 + c) * 68 + 2 * lane];
            const float2 xnc = *(const float2*)&sxn[wid * 64 + c];
            hc0 += xnc.x * wb0.x + xnc.y * wb1.x;
            hc1 += xnc.x * wb0.y + xnc.y * wb1.y;
            #pragma unroll
            for (int k = 0; k < KK; k++) {
                const float2 dv = *(const float2*)&dif[k * 64 + c];
                h0[k] += dv.x * wa0.x + dv.y * wa1.x;
                h1[k] += dv.x * wa0.y + dv.y * wa1.y;
            }
        }
        // softmax over k (two d-columns per lane)
        float m0v = -INFINITY, m1v = -INFINITY;
        #pragma unroll
        for (int k = 0; k < KK; k++) {
            h0[k] += hc0; h1[k] += hc1;
            m0v = fmaxf(m0v, h0[k]); m1v = fmaxf(m1v, h1[k]);
        }
        float s0 = 0.f, s1 = 0.f;
        #pragma unroll
        for (int k = 0; k < KK; k++) {
            h0[k] = __expf(h0[k] - m0v); s0 += h0[k];
            h1[k] = __expf(h1[k] - m1v); s1 += h1[k];
        }
        float i0 = 1.f / s0, i1 = 1.f / s1;

        // gA for c = 2*lane, 2*lane+1
        float ga = 0.f, gb = 0.f;
        #pragma unroll
        for (int k = 0; k < KK; k++) {
            const float2 dv = *(const float2*)&dif[k * 64 + 2 * lane];
            ga += dv.x * h0[k]; gb += dv.y * h1[k];
        }
        float* gp = sg + wid * 128;
        gp[2 * lane]     = ga * i0;
        gp[2 * lane + 1] = gb * i1;
        gp[64 + lane]    = xn0;      // center half: softmax sums to 1
        gp[96 + lane]    = xn1;
        __syncwarp();

        // out[o] = sum_c W2[o][c] * g[c] ; lane owns o = 4*lane..+3
        float o0 = 0.f, o1 = 0.f, o2 = 0.f, o3 = 0.f;
        #pragma unroll 4
        for (int c = 0; c < 128; c++) {
            float gv = gp[c];
            const float4 w = *(const float4*)&sW2[c * 132 + 4 * lane];
            o0 += gv * w.x; o1 += gv * w.y; o2 += gv * w.z; o3 += gv * w.w;
        }
        float* op = out + (size_t)b * NO * NN + n;
        op[(4 * lane + 0) * NN] = o0;
        op[(4 * lane + 1) * NN] = o1;
        op[(4 * lane + 2) * NN] = o2;
        op[(4 * lane + 3) * NN] = o3;
        __syncwarp();
    }
}

// ============================================================================
extern "C" void kernel_launch(void* const* d_in, const int* in_sizes, int n_in,
                              void* d_out, int out_size) {
    const float* x  = (const float*)d_in[0];
    const float* W1 = (const float*)d_in[1];
    const float* W2 = (const float*)d_in[2];
    float* out = (float*)d_out;

    cudaFuncSetAttribute(k_knn, cudaFuncAttributeMaxDynamicSharedMemorySize, KNN_SMEM);
    cudaFuncSetAttribute(k_mlp, cudaFuncAttributeMaxDynamicSharedMemorySize, MLP_SMEM);

    dim3 g1(NN / 64, NB);
    k_prep<<<g1, 256>>>(x);
    dim3 g2(NN / 32, NB);
    k_knn<<<g2, 256, KNN_SMEM>>>(x);
    k_mlp<<<148, 256, MLP_SMEM>>>(W1, W2, out);
}

// round 7
// speedup vs baseline: 2.1722x; 1.0136x over previous
#include <cuda_runtime.h>
#include <cuda_bf16.h>
#include <math.h>
#include <stdint.h>

// Round 6: tcgen05 is unusable in this harness (nvcc lowers via compute_103
// PTX, which rejects sm_103a-feature instructions). Use legacy mma.sync
// HMMA (sm_80+ PTX) for the distance GEMM instead: 2x-bf16 split (hi/lo),
// fp32 accumulation, register A-fragments, proven ballot top-20 epilogue.

#define NB 4
#define NC 64
#define NN 8192
#define NO 128
#define KK 20

// ---------------- scratch (device globals: allocation-free) ----------------
__device__ float g_xt[NB * NN * NC];            // x transposed fp32 (for k_mlp)
__device__ float g_txxh[NB * NN];               // 0.5 * ||x||^2
__device__ int   g_idx[NB * NN * KK];           // top-K neighbor sets (unsorted)
__device__ __nv_bfloat16 g_xh[NB * NN * NC];    // bf16 hi
__device__ __nv_bfloat16 g_xl[NB * NN * NC];    // bf16 lo (x - hi)

// ============================================================================
// K1: transpose + norms + bf16 hi/lo split
// ============================================================================
__global__ __launch_bounds__(256) void k_prep(const float* __restrict__ x) {
    __shared__ float t[64 * 65];
    int b = blockIdx.y;
    int n0 = blockIdx.x * 64;
    int tid = threadIdx.x;
    const float* xb = x + (size_t)b * NC * NN;

    for (int i = tid; i < 64 * 64; i += 256) {
        int c = i >> 6, nn = i & 63;
        t[c * 65 + nn] = xb[c * NN + n0 + nn];
    }
    __syncthreads();
    for (int i = tid; i < 64 * 64; i += 256) {
        int nn = i >> 6, c = i & 63;
        float v = t[c * 65 + nn];
        size_t o = ((size_t)b * NN + n0 + nn) * NC + c;
        g_xt[o] = v;
        __nv_bfloat16 h = __float2bfloat16(v);
        g_xh[o] = h;
        g_xl[o] = __float2bfloat16(v - __bfloat162float(h));
    }
    if (tid < 64) {
        float s = 0.f;
        #pragma unroll
        for (int c = 0; c < 64; c++) { float v = t[c * 65 + tid]; s += v * v; }
        g_txxh[b * NN + n0 + tid] = 0.5f * s;
    }
}

// ============================================================================
// K2: HMMA KNN. CTA = 128 rows (8 warps x m16), scans 64 col-tiles of 128.
// dot via 2xbf16 split: hi*hi + hi*lo + lo*hi, fp32 accum (mma.sync m16n8k16).
// A-frags (8 k-steps: hi k0..63, lo k64..127) cached in registers per warp.
// Per tile: 16 n-blocks x 12 k-passes of MMA; epilogue: regs -> per-warp smem
// D tile -> ballot-distributed top-20 (unsorted set; K3 is order-invariant).
// smem (bytes):
//   sD  @0       8 warps x 16 x 136 fp32 = 69632   (stride 136: STS.64 +
//                LDS.128 both bank-conflict-free)
//   sA  @69632   128 x 136 bf16 = 34816            (hi at k0..63, lo at 64..127)
//   sB  @104448  128 x 136 bf16 = 34816
// ============================================================================
#define SD_BASE 0
#define SA_BASE 69632
#define SB_BASE 104448
#define KNN_SMEM 139264

__device__ __forceinline__ void mma16816(float* c, const uint32_t* a,
                                         uint32_t b0, uint32_t b1) {
    asm volatile(
        "mma.sync.aligned.m16n8k16.row.col.f32.bf16.bf16.f32 "
        "{%0,%1,%2,%3},{%4,%5,%6,%7},{%8,%9},{%0,%1,%2,%3};"
        : "+f"(c[0]), "+f"(c[1]), "+f"(c[2]), "+f"(c[3])
        : "r"(a[0]), "r"(a[1]), "r"(a[2]), "r"(a[3]), "r"(b0), "r"(b1));
}

__global__ __launch_bounds__(256, 1) void k_knn_mma() {
    extern __shared__ char smem[];
    float* sD = (float*)(smem + SD_BASE);
    __nv_bfloat16* sA = (__nv_bfloat16*)(smem + SA_BASE);
    __nv_bfloat16* sB = (__nv_bfloat16*)(smem + SB_BASE);

    int tid = threadIdx.x, lane = tid & 31, w = tid >> 5;
    int g = lane >> 2, t = lane & 3;          // mma group / thread-in-group
    int b = blockIdx.y;
    int r0 = blockIdx.x * 128;

    // ---- load A block: 128 rows x (hi|lo) bf16, stride 136 ----
    for (int i = tid; i < 128 * 8; i += 256) {
        int r = i >> 3, j = i & 7;
        size_t go = ((size_t)b * NN + r0 + r) * NC + j * 8;
        uint4 vh = *(const uint4*)&g_xh[go];
        uint4 vl = *(const uint4*)&g_xl[go];
        *(uint4*)&sA[r * 136 + j * 8]      = vh;
        *(uint4*)&sA[r * 136 + 64 + j * 8] = vl;
    }
    __syncthreads();

    // ---- cache A fragments: 8 k-steps (0..3 hi, 4..7 lo), 4 regs each ----
    uint32_t af[8][4];
    {
        int arow = 16 * w + g;
        #pragma unroll
        for (int s = 0; s < 8; s++) {
            int koff = 16 * s;
            af[s][0] = *(const uint32_t*)&sA[arow * 136 + koff + 2 * t];
            af[s][1] = *(const uint32_t*)&sA[(arow + 8) * 136 + koff + 2 * t];
            af[s][2] = *(const uint32_t*)&sA[arow * 136 + koff + 8 + 2 * t];
            af[s][3] = *(const uint32_t*)&sA[(arow + 8) * 136 + koff + 8 + 2 * t];
        }
    }

    // ---- distributed top-20 state: lane e<20 holds entry e of each row ----
    float val[16], rmin[16]; int idxr[16];
    #pragma unroll
    for (int r = 0; r < 16; r++) {
        val[r] = (lane < KK) ? -INFINITY : INFINITY;
        idxr[r] = 0;
        rmin[r] = -INFINITY;
    }

    float* sDw = sD + w * 16 * 136;

    for (int t64 = 0; t64 < 64; t64++) {
        int m0 = t64 * 128;
        __syncthreads();                       // previous tile's sB readers done
        for (int i = tid; i < 128 * 8; i += 256) {
            int r = i >> 3, j = i & 7;
            size_t go = ((size_t)b * NN + m0 + r) * NC + j * 8;
            uint4 vh = *(const uint4*)&g_xh[go];
            uint4 vl = *(const uint4*)&g_xl[go];
            *(uint4*)&sB[r * 136 + j * 8]      = vh;
            *(uint4*)&sB[r * 136 + 64 + j * 8] = vl;
        }
        __syncthreads();

        float acc[16][4];
        #pragma unroll
        for (int nb = 0; nb < 16; nb++)
            #pragma unroll
            for (int q = 0; q < 4; q++) acc[nb][q] = 0.f;

        #pragma unroll
        for (int nb = 0; nb < 16; nb++) {
            const __nv_bfloat16* brow = sB + (nb * 8 + g) * 136 + 2 * t;
            #pragma unroll
            for (int sp = 0; sp < 12; sp++) {
                int afi  = (sp < 4) ? sp : sp - 4;             // hi,hi,lo frags
                int koff = (sp < 8) ? 16 * sp : 16 * (sp - 8); // hiB,loB,hiB
                uint32_t b0 = *(const uint32_t*)&brow[koff];
                uint32_t b1 = *(const uint32_t*)&brow[koff + 8];
                mma16816(acc[nb], af[afi], b0, b1);
            }
        }

        // ---- epilogue: regs -> per-warp D tile -> ballot selection ----
        #pragma unroll
        for (int nb = 0; nb < 16; nb++) {
            *(float2*)&sDw[g * 136 + nb * 8 + 2 * t]       = make_float2(acc[nb][0], acc[nb][1]);
            *(float2*)&sDw[(g + 8) * 136 + nb * 8 + 2 * t] = make_float2(acc[nb][2], acc[nb][3]);
        }
        __syncwarp();

        float4 txx = *(const float4*)&g_txxh[(size_t)b * NN + m0 + 4 * lane];

        #pragma unroll
        for (int r = 0; r < 16; r++) {
            const float4 v4 = *(const float4*)&sDw[r * 136 + 4 * lane];
            float pd0 = v4.x - txx.x, pd1 = v4.y - txx.y;
            float pd2 = v4.z - txx.z, pd3 = v4.w - txx.w;
            float lmax = fmaxf(fmaxf(pd0, pd1), fmaxf(pd2, pd3));
            unsigned act = __ballot_sync(0xffffffffu, lmax > rmin[r]);
            while (act) {
                int src = __ffs(act) - 1; act &= act - 1;
                #pragma unroll
                for (int q = 0; q < 4; q++) {
                    float v = __shfl_sync(0xffffffffu,
                        q == 0 ? pd0 : q == 1 ? pd1 : q == 2 ? pd2 : pd3, src);
                    if (v > rmin[r]) {                 // uniform branch
                        unsigned eq = __ballot_sync(0xffffffffu, val[r] == rmin[r]);
                        int sel = __ffs(eq) - 1;
                        if (lane == sel) { val[r] = v; idxr[r] = m0 + 4 * src + q; }
                        float mv = val[r];
                        #pragma unroll
                        for (int off = 16; off > 0; off >>= 1)
                            mv = fminf(mv, __shfl_xor_sync(0xffffffffu, mv, off));
                        rmin[r] = mv;
                    }
                }
            }
        }
    }

    if (lane < KK) {
        #pragma unroll
        for (int r = 0; r < 16; r++)
            g_idx[((size_t)b * NN + r0 + 16 * w + r) * KK + lane] = idxr[r];
    }
}

// ============================================================================
// K3: per-point gated MLP (round-2 proven version)
// ============================================================================
#define MLP_SMEM (37376 * 4)

__global__ __launch_bounds__(256) void k_mlp(const float* __restrict__ W1,
                                             const float* __restrict__ W2,
                                             float* __restrict__ out) {
    extern __shared__ float sm[];
    float* sW1h  = sm;               // [cin*68 + d]
    float* sW2   = sm + 8704;        // [c*132 + o]
    float* sdiff = sm + 25600;       // [(wid*20+k)*64 + c]
    float* sxn   = sm + 35840;       // [wid*64 + c]
    float* sg    = sm + 36352;       // [wid*128 + c]

    int tid = threadIdx.x, lane = tid & 31, wid = tid >> 5;

    for (int i = tid; i < 64 * 128; i += 256) {
        int d = i >> 7, c = i & 127;
        sW1h[c * 68 + d] = W1[i];
    }
    for (int i = tid; i < 128 * 128; i += 256) {
        int o = i >> 7, c = i & 127;
        sW2[c * 132 + o] = W2[i];
    }
    __syncthreads();

    int gw = blockIdx.x * 8 + wid;
    for (int p = gw; p < NB * NN; p += 148 * 8) {
        int b = p >> 13, n = p & (NN - 1);
        const float* xc = g_xt + (size_t)p * 64;
        float xn0 = xc[lane], xn1 = xc[lane + 32];
        sxn[wid * 64 + lane] = xn0;
        sxn[wid * 64 + lane + 32] = xn1;

        int midx = 0;
        if (lane < KK) midx = g_idx[p * KK + lane];
        #pragma unroll
        for (int k = 0; k < KK; k++) {
            int m = __shfl_sync(0xffffffffu, midx, k);
            const float* xm = g_xt + ((size_t)b * NN + m) * 64;
            sdiff[(wid * 20 + k) * 64 + lane]      = xm[lane]      - xn0;
            sdiff[(wid * 20 + k) * 64 + lane + 32] = xm[lane + 32] - xn1;
        }
        __syncwarp();

        const float* dif = sdiff + wid * 20 * 64;
        float h0[KK], h1[KK];
        #pragma unroll
        for (int k = 0; k < KK; k++) { h0[k] = 0.f; h1[k] = 0.f; }
        float hc0 = 0.f, hc1 = 0.f;
        #pragma unroll 2
        for (int c2 = 0; c2 < 32; c2++) {
            int c = 2 * c2;
            const float2 wa0 = *(const float2*)&sW1h[c * 68 + 2 * lane];
            const float2 wa1 = *(const float2*)&sW1h[(c + 1) * 68 + 2 * lane];
            const float2 wb0 = *(const float2*)&sW1h[(64 + c) * 68 + 2 * lane];
            const float2 wb1 = *(const float2*)&sW1h[(65 + c) * 68 + 2 * lane];
            const float2 xnc = *(const float2*)&sxn[wid * 64 + c];
            hc0 += xnc.x * wb0.x + xnc.y * wb1.x;
            hc1 += xnc.x * wb0.y + xnc.y * wb1.y;
            #pragma unroll
            for (int k = 0; k < KK; k++) {
                const float2 dv = *(const float2*)&dif[k * 64 + c];
                h0[k] += dv.x * wa0.x + dv.y * wa1.x;
                h1[k] += dv.x * wa0.y + dv.y * wa1.y;
            }
        }
        float m0v = -INFINITY, m1v = -INFINITY;
        #pragma unroll
        for (int k = 0; k < KK; k++) {
            h0[k] += hc0; h1[k] += hc1;
            m0v = fmaxf(m0v, h0[k]); m1v = fmaxf(m1v, h1[k]);
        }
        float s0 = 0.f, s1 = 0.f;
        #pragma unroll
        for (int k = 0; k < KK; k++) {
            h0[k] = __expf(h0[k] - m0v); s0 += h0[k];
            h1[k] = __expf(h1[k] - m1v); s1 += h1[k];
        }
        float i0 = 1.f / s0, i1 = 1.f / s1;

        float ga = 0.f, gb = 0.f;
        #pragma unroll
        for (int k = 0; k < KK; k++) {
            const float2 dv = *(const float2*)&dif[k * 64 + 2 * lane];
            ga += dv.x * h0[k]; gb += dv.y * h1[k];
        }
        float* gp = sg + wid * 128;
        gp[2 * lane]     = ga * i0;
        gp[2 * lane + 1] = gb * i1;
        gp[64 + lane]    = xn0;
        gp[96 + lane]    = xn1;
        __syncwarp();

        float o0 = 0.f, o1 = 0.f, o2 = 0.f, o3 = 0.f;
        #pragma unroll 4
        for (int c = 0; c < 128; c++) {
            float gv = gp[c];
            const float4 wv = *(const float4*)&sW2[c * 132 + 4 * lane];
            o0 += gv * wv.x; o1 += gv * wv.y; o2 += gv * wv.z; o3 += gv * wv.w;
        }
        float* op = out + (size_t)b * NO * NN + n;
        op[(4 * lane + 0) * NN] = o0;
        op[(4 * lane + 1) * NN] = o1;
        op[(4 * lane + 2) * NN] = o2;
        op[(4 * lane + 3) * NN] = o3;
        __syncwarp();
    }
}

// ============================================================================
extern "C" void kernel_launch(void* const* d_in, const int* in_sizes, int n_in,
                              void* d_out, int out_size) {
    const float* x  = (const float*)d_in[0];
    const float* W1 = (const float*)d_in[1];
    const float* W2 = (const float*)d_in[2];
    float* out = (float*)d_out;

    cudaFuncSetAttribute(k_knn_mma, cudaFuncAttributeMaxDynamicSharedMemorySize, KNN_SMEM);
    cudaFuncSetAttribute(k_mlp, cudaFuncAttributeMaxDynamicSharedMemorySize, MLP_SMEM);

    dim3 g1(NN / 64, NB);
    k_prep<<<g1, 256>>>(x);
    dim3 g2(NN / 128, NB);
    k_knn_mma<<<g2, 256, KNN_SMEM>>>();
    k_mlp<<<148, 256, MLP_SMEM>>>(W1, W2, out);
}